// round 9
// baseline (speedup 1.0000x reference)
#include <cuda_runtime.h>

// Problem constants
constexpr int BATCH = 128;
constexpr int TSEQ  = 512;
constexpr int KIN   = 906;
constexpr int NG    = 16;       // 4*H gates
constexpr int KHALF = 453;      // K split
constexpr int CK    = 16;       // k per chunk
constexpr int NCHK  = 29;       // 28*16 + 5
constexpr int PROWS = 256;      // rows per proj block
constexpr int PITCH = 258;      // k-major tile pitch (floats)

// Scratch (device globals; no allocation allowed)
// K-half partials, layout [t][b][j][ifgo]; i/f/o pre-scaled 0.5 (sigmoid fold)
__device__ __align__(16) float g_xph[2][BATCH * TSEQ * NG];
__device__ float g_hf[BATCH * 4];

// ---------- packed fp32x2 helpers (Blackwell FFMA2) ----------
__device__ __forceinline__ unsigned long long pack2(float x) {
    unsigned long long r;
    asm("mov.b64 %0, {%1, %1};" : "=l"(r) : "f"(x));
    return r;
}
__device__ __forceinline__ unsigned long long fma2(unsigned long long a,
                                                   unsigned long long b,
                                                   unsigned long long c) {
    unsigned long long d;
    asm("fma.rn.f32x2 %0, %1, %2, %3;" : "=l"(d) : "l"(a), "l"(b), "l"(c));
    return d;
}
__device__ __forceinline__ void unpack2(unsigned long long a, float& lo, float& hi) {
    asm("mov.b64 {%0, %1}, %2;" : "=f"(lo), "=f"(hi) : "l"(a));
}

// ---------- activations ----------
__device__ __forceinline__ float tanha(float x) {
    float r;
    asm("tanh.approx.f32 %0, %1;" : "=f"(r) : "f"(x));
    return r;
}
__device__ __forceinline__ float sigmoid_acc(float x) {
    float e = __expf(-x);
    return __fdividef(1.0f, 1.0f + e);
}
__device__ __forceinline__ float tanh_acc(float x) {
    float e = __expf(2.0f * x);
    return 1.0f - __fdividef(2.0f, 1.0f + e);
}

// ---------- cp.async 16B ----------
__device__ __forceinline__ void cp16(void* dst, const void* src) {
    unsigned d = (unsigned)__cvta_generic_to_shared(dst);
    asm volatile("cp.async.cg.shared.global [%0], [%1], 16;" :: "r"(d), "l"(src));
}

// =====================================================================
// Kernel 1: projection. grid (256, 2); 128 threads; R=2 rows/thread.
// R5 structure + DEPTH-2 register staging: LDG(ch+2) issued at iter ch,
// consumed by STS at end of iter ch+1 -> ~2 chunk-computes of DRAM-latency
// cover (duty-cycle fix for the 2.6 TB/s plateau).
// =====================================================================
__global__ __launch_bounds__(128) void proj_kernel(const float* __restrict__ x,
                                                   const float* __restrict__ Wih,
                                                   const float* __restrict__ bih,
                                                   const float* __restrict__ bhh) {
    __shared__ __align__(16) float sxT[2][CK * PITCH];  // [buf][k][row]
    __shared__ __align__(16) float sw[2][CK * 16];      // [buf][k][gate]

    const int tid  = threadIdx.x;
    const int lane = tid & 31;
    const int wid  = tid >> 5;
    const int half = blockIdx.y;
    const int kb   = half * KHALF;
    const size_t row0 = (size_t)blockIdx.x * PROWS;

    const int kk_l = lane & 15;     // k within chunk
    const int rs   = lane >> 4;     // row sub (0/1)

    unsigned long long accA[8], accB[8];
#pragma unroll
    for (int m = 0; m < 8; ++m) { accA[m] = 0ull; accB[m] = 0ull; }

    float xreg[2][32];   // depth-2 staging
    float wreg[2][2];

    // coalesced LDG of chunk ch into register bank rb
    auto ldg_chunk = [&](int ch, int rb) {
        const int kloc = ch * CK + kk_l;
        const bool ok = kloc < KHALF;
        const float* xp = x + (row0 + 64 * wid + rs) * KIN + kb + kloc;
#pragma unroll
        for (int i = 0; i < 32; ++i)
            xreg[rb][i] = ok ? __ldg(xp + (size_t)2 * i * KIN) : 0.0f;
        // W: 256 values, 128 threads x 2
#pragma unroll
        for (int u = 0; u < 2; ++u) {
            const int idx = tid + 128 * u;
            const int kw = idx >> 4, g = idx & 15;
            const int kwl = ch * CK + kw;
            const float sc = (g >= 8 && g < 12) ? 1.0f : 0.5f;
            wreg[rb][u] = (kwl < KHALF) ? sc * __ldg(Wih + (size_t)g * KIN + kb + kwl) : 0.0f;
        }
    };
    auto sts_chunk = [&](int rb, int buf) {
        float* sx = sxT[buf];
#pragma unroll
        for (int i = 0; i < 32; ++i)
            sx[kk_l * PITCH + 64 * wid + rs + 2 * i] = xreg[rb][i];
        float* swp = sw[buf];
#pragma unroll
        for (int u = 0; u < 2; ++u) {
            const int idx = tid + 128 * u;
            swp[idx] = wreg[rb][u];    // [k][g] layout: idx = k*16+g
        }
    };

#define PROJ_K(SX, SW, KK)                                                     \
    {                                                                          \
        const float2 xv = *(const float2*)((SX) + (KK) * PITCH + 2 * tid);     \
        const unsigned long long xa = pack2(xv.x);                             \
        const unsigned long long xb = pack2(xv.y);                             \
        const ulonglong2* wr = (const ulonglong2*)((SW) + (KK) * 16);          \
        ulonglong2 w0 = wr[0], w1 = wr[1];                                     \
        accA[0] = fma2(xa, w0.x, accA[0]);  accB[0] = fma2(xb, w0.x, accB[0]); \
        accA[1] = fma2(xa, w0.y, accA[1]);  accB[1] = fma2(xb, w0.y, accB[1]); \
        accA[2] = fma2(xa, w1.x, accA[2]);  accB[2] = fma2(xb, w1.x, accB[2]); \
        accA[3] = fma2(xa, w1.y, accA[3]);  accB[3] = fma2(xb, w1.y, accB[3]); \
        ulonglong2 w2 = wr[2], w3 = wr[3];                                     \
        accA[4] = fma2(xa, w2.x, accA[4]);  accB[4] = fma2(xb, w2.x, accB[4]); \
        accA[5] = fma2(xa, w2.y, accA[5]);  accB[5] = fma2(xb, w2.y, accB[5]); \
        accA[6] = fma2(xa, w3.x, accA[6]);  accB[6] = fma2(xb, w3.x, accB[6]); \
        accA[7] = fma2(xa, w3.y, accA[7]);  accB[7] = fma2(xb, w3.y, accB[7]); \
    }

    // depth-2 prologue: banks 0,1 hold chunks 0,1; chunk 0 staged to smem
    ldg_chunk(0, 0);
    ldg_chunk(1, 1);
    sts_chunk(0, 0);
    __syncthreads();

    for (int ch = 0; ch < NCHK; ++ch) {
        // bank (ch&1) held chunk ch, already in smem -> reuse for ch+2
        if (ch + 2 < NCHK) ldg_chunk(ch + 2, ch & 1);
        const float* sx = sxT[ch & 1];
        const float* swp = sw[ch & 1];
        if (ch < NCHK - 1) {
#pragma unroll
            for (int kk = 0; kk < CK; ++kk) PROJ_K(sx, swp, kk)
        } else {
#pragma unroll
            for (int kk = 0; kk < KHALF - CK * (NCHK - 1); ++kk) PROJ_K(sx, swp, kk)
        }
        if (ch + 1 < NCHK) sts_chunk((ch + 1) & 1, (ch + 1) & 1);
        __syncthreads();
    }
#undef PROJ_K

    // epilogue: unpack, bias (half 0, scaled), store [t][b][j][ifgo]
    float va[16], vb[16];
#pragma unroll
    for (int m = 0; m < 8; ++m) { unpack2(accA[m], va[2*m], va[2*m+1]);
                                  unpack2(accB[m], vb[2*m], vb[2*m+1]); }
    if (half == 0) {
#pragma unroll
        for (int g = 0; g < 16; ++g) {
            const float sc = (g >= 8 && g < 12) ? 1.0f : 0.5f;
            const float b = sc * (__ldg(&bih[g]) + __ldg(&bhh[g]));
            va[g] += b; vb[g] += b;
        }
    }

    float4* dst = reinterpret_cast<float4*>(g_xph[half]);
    const size_t rA = row0 + 2 * tid;
    const size_t tA = rA & 511, bA = rA >> 9;
    const size_t tB = (rA + 1) & 511, bB = (rA + 1) >> 9;
#pragma unroll
    for (int j = 0; j < 4; ++j) {
        dst[(tA * 128 + bA) * 4 + j] = make_float4(va[j], va[4+j], va[8+j], va[12+j]);
        dst[(tB * 128 + bB) * 4 + j] = make_float4(vb[j], vb[4+j], vb[8+j], vb[12+j]);
    }
}

// =====================================================================
// Kernel 2: forward LSTM, fused K-half combine. 8 blocks x 64 threads:
// warp0 = compute (16 batches, dual stream, 4 lanes/batch),
// warp1 = copy (cp.async, 16-step stages, both halves, double-buffered).
// (R5 version, measured good.)
// =====================================================================
__global__ __launch_bounds__(64) void lstm_fwd_kernel(const float* __restrict__ Whh) {
    extern __shared__ float sx[];   // [buf][half][step][b][16] = 2*2*16*16*16 floats (64 KB)
    auto buf_at = [&](int p, int h, int tt, int b) -> float* {
        return sx + (((p * 2 + h) * 16 + tt) * 16 + b) * 16;
    };

    const int tid = threadIdx.x;
    const int blk_b0 = blockIdx.x * 16;

    if (tid >= 32) {
        // ---------------- copy warp ----------------
        const int l  = tid & 31;
        const int bb = l & 15;
        const int f0 = (l >> 4) * 8;
        auto fill = [&](int s) {
            const int t0 = s * 16;
            const int p = s & 1;
#pragma unroll
            for (int h = 0; h < 2; ++h) {
                const float* base = g_xph[h];
#pragma unroll
                for (int tt = 0; tt < 16; ++tt) {
                    const float* src = base + (((size_t)(t0 + tt) * 128) + blk_b0 + bb) * 16 + f0;
                    float* d = buf_at(p, h, tt, bb) + f0;
                    cp16(d, src);
                    cp16(d + 4, src + 4);
                }
            }
        };
        fill(0);
        asm volatile("cp.async.commit_group;");
        asm volatile("cp.async.wait_group 0;" ::: "memory");
        __syncthreads();
        for (int s = 0; s < 32; ++s) {
            if (s + 1 < 32) {
                fill(s + 1);
                asm volatile("cp.async.commit_group;");
                asm volatile("cp.async.wait_group 0;" ::: "memory");
            }
            __syncthreads();
        }
    } else {
        // ---------------- compute warp ----------------
        const int j  = tid & 3;
        const int pr = tid >> 2;
        const int bA = pr, bB = pr + 8;

        // 0.25 = 0.5(sigmoid fold) * 0.5(h2 fold); g-gate 0.5 (h2 fold only)
        float wi[4], wf[4], wg[4], wo[4];
#pragma unroll
        for (int k = 0; k < 4; ++k) {
            wi[k] = 0.25f * __ldg(&Whh[(0  + j) * 4 + k]);
            wf[k] = 0.25f * __ldg(&Whh[(4  + j) * 4 + k]);
            wg[k] = 0.50f * __ldg(&Whh[(8  + j) * 4 + k]);
            wo[k] = 0.25f * __ldg(&Whh[(12 + j) * 4 + k]);
        }

        float a0 = 0.f, a1 = 0.f, a2 = 0.f, a3 = 0.f, cA = 0.f, hA2 = 0.f;
        float e0 = 0.f, e1 = 0.f, e2 = 0.f, e3 = 0.f, cB = 0.f, hB2 = 0.f;

        __syncthreads();   // matches copy prologue sync

        for (int s = 0; s < 32; ++s) {
            const int p = s & 1;
            float4 cA0 = *reinterpret_cast<const float4*>(buf_at(p, 0, 0, bA) + 4 * j);
            float4 cA1 = *reinterpret_cast<const float4*>(buf_at(p, 1, 0, bA) + 4 * j);
            float4 cB0 = *reinterpret_cast<const float4*>(buf_at(p, 0, 0, bB) + 4 * j);
            float4 cB1 = *reinterpret_cast<const float4*>(buf_at(p, 1, 0, bB) + 4 * j);
#pragma unroll
            for (int tt = 0; tt < 16; ++tt) {
                float4 nA0, nA1, nB0, nB1;
                if (tt < 15) {
                    nA0 = *reinterpret_cast<const float4*>(buf_at(p, 0, tt + 1, bA) + 4 * j);
                    nA1 = *reinterpret_cast<const float4*>(buf_at(p, 1, tt + 1, bA) + 4 * j);
                    nB0 = *reinterpret_cast<const float4*>(buf_at(p, 0, tt + 1, bB) + 4 * j);
                    nB1 = *reinterpret_cast<const float4*>(buf_at(p, 1, tt + 1, bB) + 4 * j);
                }

                // balanced trees; half-1 partial folded into second tree
                float ipA = fmaf(wi[1], a1, fmaf(wi[0], a0, cA0.x)) + fmaf(wi[3], a3, fmaf(wi[2], a2, cA1.x));
                float fpA = fmaf(wf[1], a1, fmaf(wf[0], a0, cA0.y)) + fmaf(wf[3], a3, fmaf(wf[2], a2, cA1.y));
                float gpA = fmaf(wg[1], a1, fmaf(wg[0], a0, cA0.z)) + fmaf(wg[3], a3, fmaf(wg[2], a2, cA1.z));
                float opA = fmaf(wo[1], a1, fmaf(wo[0], a0, cA0.w)) + fmaf(wo[3], a3, fmaf(wo[2], a2, cA1.w));
                float ipB = fmaf(wi[1], e1, fmaf(wi[0], e0, cB0.x)) + fmaf(wi[3], e3, fmaf(wi[2], e2, cB1.x));
                float fpB = fmaf(wf[1], e1, fmaf(wf[0], e0, cB0.y)) + fmaf(wf[3], e3, fmaf(wf[2], e2, cB1.y));
                float gpB = fmaf(wg[1], e1, fmaf(wg[0], e0, cB0.z)) + fmaf(wg[3], e3, fmaf(wg[2], e2, cB1.z));
                float opB = fmaf(wo[1], e1, fmaf(wo[0], e0, cB0.w)) + fmaf(wo[3], e3, fmaf(wo[2], e2, cB1.w));

                const float tiA = tanha(ipA), tfA = tanha(fpA), tgA = tanha(gpA), toA = tanha(opA);
                const float tiB = tanha(ipB), tfB = tanha(fpB), tgB = tanha(gpB), toB = tanha(opB);

                cA = 0.5f * (fmaf(tfA, cA, cA) + fmaf(tiA, tgA, tgA));
                cB = 0.5f * (fmaf(tfB, cB, cB) + fmaf(tiB, tgB, tgB));

                const float tcA = tanha(cA);
                const float tcB = tanha(cB);
                hA2 = fmaf(toA, tcA, tcA);   // = 2*h
                hB2 = fmaf(toB, tcB, tcB);

                a0 = __shfl_sync(0xffffffffu, hA2, 0, 4);
                a1 = __shfl_sync(0xffffffffu, hA2, 1, 4);
                a2 = __shfl_sync(0xffffffffu, hA2, 2, 4);
                a3 = __shfl_sync(0xffffffffu, hA2, 3, 4);
                e0 = __shfl_sync(0xffffffffu, hB2, 0, 4);
                e1 = __shfl_sync(0xffffffffu, hB2, 1, 4);
                e2 = __shfl_sync(0xffffffffu, hB2, 2, 4);
                e3 = __shfl_sync(0xffffffffu, hB2, 3, 4);

                cA0 = nA0; cA1 = nA1; cB0 = nB0; cB1 = nB1;
            }
            __syncthreads();
        }

        g_hf[(blk_b0 + bA) * 4 + j] = 0.5f * hA2;
        g_hf[(blk_b0 + bB) * 4 + j] = 0.5f * hB2;
    }
}

// =====================================================================
// Kernel 3: tail. 128 blocks x 384 threads; warp w reduces one live gate
// row (i: 0-3, g: 8-11, o: 12-15). f-gate provably unused (c0 = 0).
// =====================================================================
__global__ __launch_bounds__(384) void tail_kernel(const float* __restrict__ x,
                                                   const float* __restrict__ Wihb,
                                                   const float* __restrict__ bihb,
                                                   const float* __restrict__ bhhb,
                                                   const float* __restrict__ Wout,
                                                   const float* __restrict__ bout,
                                                   float* __restrict__ out) {
    const int b = blockIdx.x;
    const int tid = threadIdx.x;
    const int w = tid >> 5;
    const int l = tid & 31;
    const int gr = (w < 4) ? w : (w + 4);    // gate row: 0-3, 8-11, 12-15

    __shared__ float sg[12];

    const float* xr = x + ((size_t)b * TSEQ + (TSEQ - 1)) * KIN;
    const float* wr = Wihb + (size_t)gr * KIN;

    float a = 0.f;
    for (int k = l; k < KIN; k += 32)
        a = fmaf(__ldg(&xr[k]), __ldg(&wr[k]), a);
#pragma unroll
    for (int s = 16; s > 0; s >>= 1)
        a += __shfl_xor_sync(0xffffffffu, a, s);
    if (l == 0) sg[w] = a + __ldg(&bihb[gr]) + __ldg(&bhhb[gr]);
    __syncthreads();

    if (tid == 0) {
        float hb[4], hf[4];
#pragma unroll
        for (int jj = 0; jj < 4; ++jj) {
            float iv = sigmoid_acc(sg[jj]);
            float gv = tanh_acc(sg[4 + jj]);
            float ov = sigmoid_acc(sg[8 + jj]);
            float cc = iv * gv;                 // c0 = 0 => f-gate drops out
            hb[jj] = ov * tanh_acc(cc);
            hf[jj] = g_hf[b * 4 + jj];
        }
#pragma unroll
        for (int o2 = 0; o2 < 2; ++o2) {
            float s = __ldg(&bout[o2]);
#pragma unroll
            for (int jj = 0; jj < 4; ++jj) {
                s = fmaf(__ldg(&Wout[o2 * 8 + jj]),     hf[jj], s);
                s = fmaf(__ldg(&Wout[o2 * 8 + 4 + jj]), hb[jj], s);
            }
            out[b * 2 + o2] = s;
        }
    }
}

// =====================================================================
extern "C" void kernel_launch(void* const* d_in, const int* in_sizes, int n_in,
                              void* d_out, int out_size) {
    const float* x    = (const float*)d_in[0];
    const float* Wihf = (const float*)d_in[1];
    const float* Whhf = (const float*)d_in[2];
    const float* bihf = (const float*)d_in[3];
    const float* bhhf = (const float*)d_in[4];
    const float* Wihb = (const float*)d_in[5];
    // d_in[6] = W_hh_b: provably unused (backward output only needs step 1 from zero state)
    const float* bihb = (const float*)d_in[7];
    const float* bhhb = (const float*)d_in[8];
    const float* Wout = (const float*)d_in[9];
    const float* bout = (const float*)d_in[10];
    float* out = (float*)d_out;

    constexpr int LSTM_SMEM = 2 * 2 * 16 * 16 * 16 * 4;   // 65536 B
    static bool attr_set = false;
    if (!attr_set) {
        cudaFuncSetAttribute(lstm_fwd_kernel, cudaFuncAttributeMaxDynamicSharedMemorySize, LSTM_SMEM);
        attr_set = true;
    }

    dim3 pgrid(BATCH * TSEQ / PROWS, 2);   // (256, 2)
    proj_kernel<<<pgrid, 128>>>(x, Wihf, bihf, bhhf);
    lstm_fwd_kernel<<<8, 64, LSTM_SMEM>>>(Whhf);
    tail_kernel<<<BATCH, 384>>>(x, Wihb, bihb, bhhb, Wout, bout, out);
}

// round 10
// speedup vs baseline: 1.8495x; 1.8495x over previous
#include <cuda_runtime.h>

// Problem constants
constexpr int BATCH = 128;
constexpr int TSEQ  = 512;
constexpr int KIN   = 906;
constexpr int NG    = 16;       // 4*H gates
constexpr int KHALF = 453;      // K split
constexpr int CK    = 16;       // k per chunk
constexpr int NCHK  = 29;       // 28*16 + 5
constexpr int PROWS = 256;      // rows per proj block
constexpr int PITCH = 258;      // k-major tile pitch (floats)

// Scratch (device globals; no allocation allowed)
// K-half partials, layout [t][b][j][ifgo]; i/f/o pre-scaled 0.5 (sigmoid fold)
__device__ __align__(16) float g_xph[2][BATCH * TSEQ * NG];
__device__ float g_hf[BATCH * 4];

// ---------- packed fp32x2 helpers (Blackwell FFMA2) ----------
__device__ __forceinline__ unsigned long long pack2(float x) {
    unsigned long long r;
    asm("mov.b64 %0, {%1, %1};" : "=l"(r) : "f"(x));
    return r;
}
__device__ __forceinline__ unsigned long long fma2(unsigned long long a,
                                                   unsigned long long b,
                                                   unsigned long long c) {
    unsigned long long d;
    asm("fma.rn.f32x2 %0, %1, %2, %3;" : "=l"(d) : "l"(a), "l"(b), "l"(c));
    return d;
}
__device__ __forceinline__ void unpack2(unsigned long long a, float& lo, float& hi) {
    asm("mov.b64 {%0, %1}, %2;" : "=f"(lo), "=f"(hi) : "l"(a));
}

// ---------- activations ----------
__device__ __forceinline__ float tanha(float x) {
    float r;
    asm("tanh.approx.f32 %0, %1;" : "=f"(r) : "f"(x));
    return r;
}
__device__ __forceinline__ float sigmoid_acc(float x) {
    float e = __expf(-x);
    return __fdividef(1.0f, 1.0f + e);
}
__device__ __forceinline__ float tanh_acc(float x) {
    float e = __expf(2.0f * x);
    return 1.0f - __fdividef(2.0f, 1.0f + e);
}

// ---------- cp.async 16B ----------
__device__ __forceinline__ void cp16(void* dst, const void* src) {
    unsigned d = (unsigned)__cvta_generic_to_shared(dst);
    asm volatile("cp.async.cg.shared.global [%0], [%1], 16;" :: "r"(d), "l"(src));
}

// =====================================================================
// Kernel 1: projection. grid (256, 2); 128 threads; R=2 rows/thread.
// R5 structure + TRUE depth-2 staging: statically-named register banks
// (xr0/xr1) + loop unrolled by 2 so bank choice is compile-time.
// LDG(ch+2) issues at iter ch, STS at end of iter ch+1 -> ~2 chunk-
// computes of DRAM-latency cover.
// =====================================================================
__global__ __launch_bounds__(128) void proj_kernel(const float* __restrict__ x,
                                                   const float* __restrict__ Wih,
                                                   const float* __restrict__ bih,
                                                   const float* __restrict__ bhh) {
    __shared__ __align__(16) float sxT[2][CK * PITCH];  // [buf][k][row]
    __shared__ __align__(16) float sw[2][CK * 16];      // [buf][k][gate]

    const int tid  = threadIdx.x;
    const int lane = tid & 31;
    const int wid  = tid >> 5;
    const int half = blockIdx.y;
    const int kb   = half * KHALF;
    const size_t row0 = (size_t)blockIdx.x * PROWS;

    const int kk_l = lane & 15;     // k within chunk
    const int rs   = lane >> 4;     // row sub (0/1)

    unsigned long long accA[8], accB[8];
#pragma unroll
    for (int m = 0; m < 8; ++m) { accA[m] = 0ull; accB[m] = 0ull; }

    float xr0[32], xr1[32];   // STATIC depth-2 banks
    float wr0[2],  wr1[2];

    // coalesced LDG of chunk ch into the given bank (array refs -> regs)
    auto ldg_chunk = [&](int ch, float (&xr)[32], float (&wr)[2]) {
        const int kloc = ch * CK + kk_l;
        const bool ok = kloc < KHALF;
        const float* xp = x + (row0 + 64 * wid + rs) * KIN + kb + kloc;
#pragma unroll
        for (int i = 0; i < 32; ++i)
            xr[i] = ok ? __ldg(xp + (size_t)2 * i * KIN) : 0.0f;
#pragma unroll
        for (int u = 0; u < 2; ++u) {
            const int idx = tid + 128 * u;
            const int kw = idx >> 4, g = idx & 15;
            const int kwl = ch * CK + kw;
            const float sc = (g >= 8 && g < 12) ? 1.0f : 0.5f;
            wr[u] = (kwl < KHALF) ? sc * __ldg(Wih + (size_t)g * KIN + kb + kwl) : 0.0f;
        }
    };
    auto sts_chunk = [&](const float (&xr)[32], const float (&wr)[2], int buf) {
        float* sx = sxT[buf];
#pragma unroll
        for (int i = 0; i < 32; ++i)
            sx[kk_l * PITCH + 64 * wid + rs + 2 * i] = xr[i];
        float* swp = sw[buf];
#pragma unroll
        for (int u = 0; u < 2; ++u)
            swp[tid + 128 * u] = wr[u];    // [k][g] layout: idx = k*16+g
    };

#define PROJ_K(SX, SW, KK)                                                     \
    {                                                                          \
        const float2 xv = *(const float2*)((SX) + (KK) * PITCH + 2 * tid);     \
        const unsigned long long xa = pack2(xv.x);                             \
        const unsigned long long xb = pack2(xv.y);                             \
        const ulonglong2* wr = (const ulonglong2*)((SW) + (KK) * 16);          \
        ulonglong2 w0 = wr[0], w1 = wr[1];                                     \
        accA[0] = fma2(xa, w0.x, accA[0]);  accB[0] = fma2(xb, w0.x, accB[0]); \
        accA[1] = fma2(xa, w0.y, accA[1]);  accB[1] = fma2(xb, w0.y, accB[1]); \
        accA[2] = fma2(xa, w1.x, accA[2]);  accB[2] = fma2(xb, w1.x, accB[2]); \
        accA[3] = fma2(xa, w1.y, accA[3]);  accB[3] = fma2(xb, w1.y, accB[3]); \
        ulonglong2 w2 = wr[2], w3 = wr[3];                                     \
        accA[4] = fma2(xa, w2.x, accA[4]);  accB[4] = fma2(xb, w2.x, accB[4]); \
        accA[5] = fma2(xa, w2.y, accA[5]);  accB[5] = fma2(xb, w2.y, accB[5]); \
        accA[6] = fma2(xa, w3.x, accA[6]);  accB[6] = fma2(xb, w3.x, accB[6]); \
        accA[7] = fma2(xa, w3.y, accA[7]);  accB[7] = fma2(xb, w3.y, accB[7]); \
    }

    // depth-2 prologue: banks hold chunks 0,1; chunk 0 staged to smem buf0
    ldg_chunk(0, xr0, wr0);
    ldg_chunk(1, xr1, wr1);
    sts_chunk(xr0, wr0, 0);
    __syncthreads();

    // 14 even/odd pairs cover chunks 0..27; chunk 28 handled after.
#pragma unroll 1
    for (int c2 = 0; c2 < 14; ++c2) {
        const int ch = 2 * c2;
        // ---- even body: consumes buf0 (chunk ch), bank0 free -> load ch+2
        ldg_chunk(ch + 2, xr0, wr0);
        {
            const float* sx = sxT[0];
            const float* swp = sw[0];
#pragma unroll
            for (int kk = 0; kk < CK; ++kk) PROJ_K(sx, swp, kk)
        }
        sts_chunk(xr1, wr1, 1);          // stage chunk ch+1 into buf1
        __syncthreads();
        // ---- odd body: consumes buf1 (chunk ch+1), bank1 free -> load ch+3
        if (ch + 3 < NCHK) ldg_chunk(ch + 3, xr1, wr1);
        {
            const float* sx = sxT[1];
            const float* swp = sw[1];
#pragma unroll
            for (int kk = 0; kk < CK; ++kk) PROJ_K(sx, swp, kk)
        }
        sts_chunk(xr0, wr0, 0);          // stage chunk ch+2 into buf0
        __syncthreads();
    }
    // ---- final chunk 28 (5 valid k) in buf0
    {
        const float* sx = sxT[0];
        const float* swp = sw[0];
#pragma unroll
        for (int kk = 0; kk < KHALF - CK * (NCHK - 1); ++kk) PROJ_K(sx, swp, kk)
    }
#undef PROJ_K

    // epilogue: unpack, bias (half 0, scaled), store [t][b][j][ifgo]
    float va[16], vb[16];
#pragma unroll
    for (int m = 0; m < 8; ++m) { unpack2(accA[m], va[2*m], va[2*m+1]);
                                  unpack2(accB[m], vb[2*m], vb[2*m+1]); }
    if (half == 0) {
#pragma unroll
        for (int g = 0; g < 16; ++g) {
            const float sc = (g >= 8 && g < 12) ? 1.0f : 0.5f;
            const float b = sc * (__ldg(&bih[g]) + __ldg(&bhh[g]));
            va[g] += b; vb[g] += b;
        }
    }

    float4* dst = reinterpret_cast<float4*>(g_xph[half]);
    const size_t rA = row0 + 2 * tid;
    const size_t tA = rA & 511, bA = rA >> 9;
    const size_t tB = (rA + 1) & 511, bB = (rA + 1) >> 9;
#pragma unroll
    for (int j = 0; j < 4; ++j) {
        dst[(tA * 128 + bA) * 4 + j] = make_float4(va[j], va[4+j], va[8+j], va[12+j]);
        dst[(tB * 128 + bB) * 4 + j] = make_float4(vb[j], vb[4+j], vb[8+j], vb[12+j]);
    }
}

// =====================================================================
// Kernel 2: forward LSTM, fused K-half combine. 8 blocks x 64 threads:
// warp0 = compute (16 batches, dual stream, 4 lanes/batch),
// warp1 = copy (cp.async, 16-step stages, both halves, double-buffered).
// (R5 version, measured good.)
// =====================================================================
__global__ __launch_bounds__(64) void lstm_fwd_kernel(const float* __restrict__ Whh) {
    extern __shared__ float sx[];   // [buf][half][step][b][16] = 2*2*16*16*16 floats (64 KB)
    auto buf_at = [&](int p, int h, int tt, int b) -> float* {
        return sx + (((p * 2 + h) * 16 + tt) * 16 + b) * 16;
    };

    const int tid = threadIdx.x;
    const int blk_b0 = blockIdx.x * 16;

    if (tid >= 32) {
        // ---------------- copy warp ----------------
        const int l  = tid & 31;
        const int bb = l & 15;
        const int f0 = (l >> 4) * 8;
        auto fill = [&](int s) {
            const int t0 = s * 16;
            const int p = s & 1;
#pragma unroll
            for (int h = 0; h < 2; ++h) {
                const float* base = g_xph[h];
#pragma unroll
                for (int tt = 0; tt < 16; ++tt) {
                    const float* src = base + (((size_t)(t0 + tt) * 128) + blk_b0 + bb) * 16 + f0;
                    float* d = buf_at(p, h, tt, bb) + f0;
                    cp16(d, src);
                    cp16(d + 4, src + 4);
                }
            }
        };
        fill(0);
        asm volatile("cp.async.commit_group;");
        asm volatile("cp.async.wait_group 0;" ::: "memory");
        __syncthreads();
        for (int s = 0; s < 32; ++s) {
            if (s + 1 < 32) {
                fill(s + 1);
                asm volatile("cp.async.commit_group;");
                asm volatile("cp.async.wait_group 0;" ::: "memory");
            }
            __syncthreads();
        }
    } else {
        // ---------------- compute warp ----------------
        const int j  = tid & 3;
        const int pr = tid >> 2;
        const int bA = pr, bB = pr + 8;

        // 0.25 = 0.5(sigmoid fold) * 0.5(h2 fold); g-gate 0.5 (h2 fold only)
        float wi[4], wf[4], wg[4], wo[4];
#pragma unroll
        for (int k = 0; k < 4; ++k) {
            wi[k] = 0.25f * __ldg(&Whh[(0  + j) * 4 + k]);
            wf[k] = 0.25f * __ldg(&Whh[(4  + j) * 4 + k]);
            wg[k] = 0.50f * __ldg(&Whh[(8  + j) * 4 + k]);
            wo[k] = 0.25f * __ldg(&Whh[(12 + j) * 4 + k]);
        }

        float a0 = 0.f, a1 = 0.f, a2 = 0.f, a3 = 0.f, cA = 0.f, hA2 = 0.f;
        float e0 = 0.f, e1 = 0.f, e2 = 0.f, e3 = 0.f, cB = 0.f, hB2 = 0.f;

        __syncthreads();   // matches copy prologue sync

        for (int s = 0; s < 32; ++s) {
            const int p = s & 1;
            float4 cA0 = *reinterpret_cast<const float4*>(buf_at(p, 0, 0, bA) + 4 * j);
            float4 cA1 = *reinterpret_cast<const float4*>(buf_at(p, 1, 0, bA) + 4 * j);
            float4 cB0 = *reinterpret_cast<const float4*>(buf_at(p, 0, 0, bB) + 4 * j);
            float4 cB1 = *reinterpret_cast<const float4*>(buf_at(p, 1, 0, bB) + 4 * j);
#pragma unroll
            for (int tt = 0; tt < 16; ++tt) {
                float4 nA0, nA1, nB0, nB1;
                if (tt < 15) {
                    nA0 = *reinterpret_cast<const float4*>(buf_at(p, 0, tt + 1, bA) + 4 * j);
                    nA1 = *reinterpret_cast<const float4*>(buf_at(p, 1, tt + 1, bA) + 4 * j);
                    nB0 = *reinterpret_cast<const float4*>(buf_at(p, 0, tt + 1, bB) + 4 * j);
                    nB1 = *reinterpret_cast<const float4*>(buf_at(p, 1, tt + 1, bB) + 4 * j);
                }

                // balanced trees; half-1 partial folded into second tree
                float ipA = fmaf(wi[1], a1, fmaf(wi[0], a0, cA0.x)) + fmaf(wi[3], a3, fmaf(wi[2], a2, cA1.x));
                float fpA = fmaf(wf[1], a1, fmaf(wf[0], a0, cA0.y)) + fmaf(wf[3], a3, fmaf(wf[2], a2, cA1.y));
                float gpA = fmaf(wg[1], a1, fmaf(wg[0], a0, cA0.z)) + fmaf(wg[3], a3, fmaf(wg[2], a2, cA1.z));
                float opA = fmaf(wo[1], a1, fmaf(wo[0], a0, cA0.w)) + fmaf(wo[3], a3, fmaf(wo[2], a2, cA1.w));
                float ipB = fmaf(wi[1], e1, fmaf(wi[0], e0, cB0.x)) + fmaf(wi[3], e3, fmaf(wi[2], e2, cB1.x));
                float fpB = fmaf(wf[1], e1, fmaf(wf[0], e0, cB0.y)) + fmaf(wf[3], e3, fmaf(wf[2], e2, cB1.y));
                float gpB = fmaf(wg[1], e1, fmaf(wg[0], e0, cB0.z)) + fmaf(wg[3], e3, fmaf(wg[2], e2, cB1.z));
                float opB = fmaf(wo[1], e1, fmaf(wo[0], e0, cB0.w)) + fmaf(wo[3], e3, fmaf(wo[2], e2, cB1.w));

                const float tiA = tanha(ipA), tfA = tanha(fpA), tgA = tanha(gpA), toA = tanha(opA);
                const float tiB = tanha(ipB), tfB = tanha(fpB), tgB = tanha(gpB), toB = tanha(opB);

                cA = 0.5f * (fmaf(tfA, cA, cA) + fmaf(tiA, tgA, tgA));
                cB = 0.5f * (fmaf(tfB, cB, cB) + fmaf(tiB, tgB, tgB));

                const float tcA = tanha(cA);
                const float tcB = tanha(cB);
                hA2 = fmaf(toA, tcA, tcA);   // = 2*h
                hB2 = fmaf(toB, tcB, tcB);

                a0 = __shfl_sync(0xffffffffu, hA2, 0, 4);
                a1 = __shfl_sync(0xffffffffu, hA2, 1, 4);
                a2 = __shfl_sync(0xffffffffu, hA2, 2, 4);
                a3 = __shfl_sync(0xffffffffu, hA2, 3, 4);
                e0 = __shfl_sync(0xffffffffu, hB2, 0, 4);
                e1 = __shfl_sync(0xffffffffu, hB2, 1, 4);
                e2 = __shfl_sync(0xffffffffu, hB2, 2, 4);
                e3 = __shfl_sync(0xffffffffu, hB2, 3, 4);

                cA0 = nA0; cA1 = nA1; cB0 = nB0; cB1 = nB1;
            }
            __syncthreads();
        }

        g_hf[(blk_b0 + bA) * 4 + j] = 0.5f * hA2;
        g_hf[(blk_b0 + bB) * 4 + j] = 0.5f * hB2;
    }
}

// =====================================================================
// Kernel 3: tail. 128 blocks x 384 threads; warp w reduces one live gate
// row (i: 0-3, g: 8-11, o: 12-15). f-gate provably unused (c0 = 0).
// =====================================================================
__global__ __launch_bounds__(384) void tail_kernel(const float* __restrict__ x,
                                                   const float* __restrict__ Wihb,
                                                   const float* __restrict__ bihb,
                                                   const float* __restrict__ bhhb,
                                                   const float* __restrict__ Wout,
                                                   const float* __restrict__ bout,
                                                   float* __restrict__ out) {
    const int b = blockIdx.x;
    const int tid = threadIdx.x;
    const int w = tid >> 5;
    const int l = tid & 31;
    const int gr = (w < 4) ? w : (w + 4);    // gate row: 0-3, 8-11, 12-15

    __shared__ float sg[12];

    const float* xr = x + ((size_t)b * TSEQ + (TSEQ - 1)) * KIN;
    const float* wr = Wihb + (size_t)gr * KIN;

    float a = 0.f;
    for (int k = l; k < KIN; k += 32)
        a = fmaf(__ldg(&xr[k]), __ldg(&wr[k]), a);
#pragma unroll
    for (int s = 16; s > 0; s >>= 1)
        a += __shfl_xor_sync(0xffffffffu, a, s);
    if (l == 0) sg[w] = a + __ldg(&bihb[gr]) + __ldg(&bhhb[gr]);
    __syncthreads();

    if (tid == 0) {
        float hb[4], hf[4];
#pragma unroll
        for (int jj = 0; jj < 4; ++jj) {
            float iv = sigmoid_acc(sg[jj]);
            float gv = tanh_acc(sg[4 + jj]);
            float ov = sigmoid_acc(sg[8 + jj]);
            float cc = iv * gv;                 // c0 = 0 => f-gate drops out
            hb[jj] = ov * tanh_acc(cc);
            hf[jj] = g_hf[b * 4 + jj];
        }
#pragma unroll
        for (int o2 = 0; o2 < 2; ++o2) {
            float s = __ldg(&bout[o2]);
#pragma unroll
            for (int jj = 0; jj < 4; ++jj) {
                s = fmaf(__ldg(&Wout[o2 * 8 + jj]),     hf[jj], s);
                s = fmaf(__ldg(&Wout[o2 * 8 + 4 + jj]), hb[jj], s);
            }
            out[b * 2 + o2] = s;
        }
    }
}

// =====================================================================
extern "C" void kernel_launch(void* const* d_in, const int* in_sizes, int n_in,
                              void* d_out, int out_size) {
    const float* x    = (const float*)d_in[0];
    const float* Wihf = (const float*)d_in[1];
    const float* Whhf = (const float*)d_in[2];
    const float* bihf = (const float*)d_in[3];
    const float* bhhf = (const float*)d_in[4];
    const float* Wihb = (const float*)d_in[5];
    // d_in[6] = W_hh_b: provably unused (backward output only needs step 1 from zero state)
    const float* bihb = (const float*)d_in[7];
    const float* bhhb = (const float*)d_in[8];
    const float* Wout = (const float*)d_in[9];
    const float* bout = (const float*)d_in[10];
    float* out = (float*)d_out;

    constexpr int LSTM_SMEM = 2 * 2 * 16 * 16 * 16 * 4;   // 65536 B
    static bool attr_set = false;
    if (!attr_set) {
        cudaFuncSetAttribute(lstm_fwd_kernel, cudaFuncAttributeMaxDynamicSharedMemorySize, LSTM_SMEM);
        attr_set = true;
    }

    dim3 pgrid(BATCH * TSEQ / PROWS, 2);   // (256, 2)
    proj_kernel<<<pgrid, 128>>>(x, Wihf, bihf, bhhf);
    lstm_fwd_kernel<<<8, 64, LSTM_SMEM>>>(Whhf);
    tail_kernel<<<BATCH, 384>>>(x, Wihb, bihb, bhhb, Wout, bout, out);
}